// round 2
// baseline (speedup 1.0000x reference)
#include <cuda_runtime.h>
#include <cuda_bf16.h>
#include <cstdint>
#include <cstddef>

#define NROWS_MAX 16384
#define DDIM 256
#define TILE_M 128
#define TILE_N 128
#define ROWW 132          // padded row width in 32-bit words (264 bf16 = 528B) -> conflict-free LDS
#define NTHREADS 256
// smem: A(128x132 words) + B0 + B1 + rowsum(128 f) + red(8 f)
#define SMEM_WORDS (3*TILE_M*ROWW + TILE_M + 8)
#define SMEM_BYTES (SMEM_WORDS*4)

__device__ __align__(16) __nv_bfloat16 g_Xh[NROWS_MAX*DDIM];
__device__ __align__(16) __nv_bfloat16 g_Yh[NROWS_MAX*DDIM];
__device__ float  g_Sv[NROWS_MAX];
__device__ double g_acc;

static __device__ __forceinline__ uint32_t smem_addr_u32(const void* p){
    return (uint32_t)__cvta_generic_to_shared(p);
}
static __device__ __forceinline__ void cp16(void* dst, const void* src){
    asm volatile("cp.async.cg.shared.global [%0], [%1], 16;\n"
                 :: "r"(smem_addr_u32(dst)), "l"(src));
}
static __device__ __forceinline__ void cp_commit(){
    asm volatile("cp.async.commit_group;\n");
}
template<int N> static __device__ __forceinline__ void cp_wait(){
    asm volatile("cp.async.wait_group %0;\n" :: "n"(N));
}
static __device__ __forceinline__ float ex2f_fast(float x){
    float r; asm("ex2.approx.ftz.f32 %0, %1;" : "=f"(r) : "f"(x)); return r;
}

// ---------------- normalize: fp32 row -> unit-norm bf16 row ----------------
__global__ void norm_kernel(const float* __restrict__ in, int which, int nrows){
    int gw   = (blockIdx.x*blockDim.x + threadIdx.x) >> 5;
    int lane = threadIdx.x & 31;
    if (gw >= nrows) return;
    const float4* rp = reinterpret_cast<const float4*>(in) + (size_t)gw*(DDIM/4);
    float4 v0 = rp[lane*2 + 0];
    float4 v1 = rp[lane*2 + 1];
    float ss = v0.x*v0.x + v0.y*v0.y + v0.z*v0.z + v0.w*v0.w
             + v1.x*v1.x + v1.y*v1.y + v1.z*v1.z + v1.w*v1.w;
    #pragma unroll
    for (int o=16;o;o>>=1) ss += __shfl_xor_sync(0xffffffffu, ss, o);
    float inv = 1.0f / fmaxf(sqrtf(ss), 1e-12f);
    __align__(16) __nv_bfloat16 h[8];
    h[0]=__float2bfloat16(v0.x*inv); h[1]=__float2bfloat16(v0.y*inv);
    h[2]=__float2bfloat16(v0.z*inv); h[3]=__float2bfloat16(v0.w*inv);
    h[4]=__float2bfloat16(v1.x*inv); h[5]=__float2bfloat16(v1.y*inv);
    h[6]=__float2bfloat16(v1.z*inv); h[7]=__float2bfloat16(v1.w*inv);
    __nv_bfloat16* out = which ? g_Yh : g_Xh;
    reinterpret_cast<uint4*>(out + (size_t)gw*DDIM)[lane] = *reinterpret_cast<uint4*>(h);
}

// ---------------- Sv diagonal (fp32), transformed: (dot-1)/t ; zero acc ----------------
__global__ void sv_kernel(const float* __restrict__ X, const float* __restrict__ Y, int nrows){
    if (blockIdx.x==0 && threadIdx.x==0) g_acc = 0.0;
    int gw   = (blockIdx.x*blockDim.x + threadIdx.x) >> 5;
    int lane = threadIdx.x & 31;
    if (gw >= nrows) return;
    const float4* xp = reinterpret_cast<const float4*>(X) + (size_t)gw*(DDIM/4);
    const float4* yp = reinterpret_cast<const float4*>(Y) + (size_t)gw*(DDIM/4);
    float dot=0.f, ssx=0.f, ssy=0.f;
    #pragma unroll
    for (int j=0;j<2;j++){
        float4 x = xp[lane*2+j], y = yp[lane*2+j];
        dot += x.x*y.x + x.y*y.y + x.z*y.z + x.w*y.w;
        ssx += x.x*x.x + x.y*x.y + x.z*x.z + x.w*x.w;
        ssy += y.x*y.x + y.y*y.y + y.z*y.z + y.w*y.w;
    }
    #pragma unroll
    for (int o=16;o;o>>=1){
        dot += __shfl_xor_sync(0xffffffffu, dot, o);
        ssx += __shfl_xor_sync(0xffffffffu, ssx, o);
        ssy += __shfl_xor_sync(0xffffffffu, ssy, o);
    }
    if (lane==0){
        float d = dot / (fmaxf(sqrtf(ssx),1e-12f) * fmaxf(sqrtf(ssy),1e-12f));
        g_Sv[gw] = (d - 1.0f) * 14.285714285714286f;   // (dot-1)/0.07
    }
}

// ---------------- main fused GEMM + exp + row-sum ----------------
__global__ void __launch_bounds__(NTHREADS, 1) lit_main_kernel(int nrows){
    extern __shared__ uint32_t smem[];
    uint32_t* As  = smem;
    uint32_t* Bs0 = smem + TILE_M*ROWW;
    uint32_t* Bs1 = Bs0 + TILE_N*ROWW;
    float* rowsum_sm = (float*)(Bs1 + TILE_N*ROWW);
    float* red_sm    = rowsum_sm + TILE_M;

    const int tid  = threadIdx.x;
    const int lane = tid & 31, wid = tid >> 5;
    const int wm = wid >> 1, wn = wid & 1;       // 4x2 warp grid (M x N)
    const int g = lane >> 2, t = lane & 3;
    const int cta = blockIdx.x;
    const int nTiles = nrows / TILE_N;

    if (tid < TILE_M) rowsum_sm[tid] = 0.0f;

    // prologue: stage full A tile (K=256 resident) + B tile 0, one cp.async group
    {
        const __nv_bfloat16* Xg = g_Xh + (size_t)cta*TILE_M*DDIM;
        #pragma unroll
        for (int j=0;j<16;j++){
            int idx = tid + NTHREADS*j;          // 4096 16B chunks
            int r = idx >> 5, c = idx & 31;
            cp16(As + r*ROWW + c*4, Xg + r*DDIM + c*8);
        }
        const __nv_bfloat16* Yg = g_Yh;
        #pragma unroll
        for (int j=0;j<16;j++){
            int idx = tid + NTHREADS*j;
            int r = idx >> 5, c = idx & 31;
            cp16(Bs0 + r*ROWW + c*4, Yg + r*DDIM + c*8);
        }
        cp_commit();
    }

    float acc[2][8][4];
    #pragma unroll
    for (int mc=0;mc<2;mc++)
        #pragma unroll
        for (int nc=0;nc<8;nc++)
            #pragma unroll
            for (int i=0;i<4;i++) acc[mc][nc][i]=0.f;
    float rowsum[4] = {0.f,0.f,0.f,0.f};

    const float Kc = 20.609929155556602f;   // log2(e)/0.07 ; exp((s-1)/t)=2^(s*Kc-Kc)
    const uint32_t* Ap = As + (wm*32 + g)*ROWW + t;

    #pragma unroll 1
    for (int it=0; it<nTiles; ++it){
        if (it+1 < nTiles){
            uint32_t* Bw = ((it+1)&1) ? Bs1 : Bs0;
            const __nv_bfloat16* Yg = g_Yh + (size_t)(it+1)*TILE_N*DDIM;
            #pragma unroll
            for (int j=0;j<16;j++){
                int idx = tid + NTHREADS*j;
                int r = idx >> 5, c = idx & 31;
                cp16(Bw + r*ROWW + c*4, Yg + r*DDIM + c*8);
            }
            cp_commit();
            cp_wait<1>();
        } else {
            cp_wait<0>();
        }
        __syncthreads();

        const uint32_t* Bs = (it&1) ? Bs1 : Bs0;
        const uint32_t* Bp = Bs + (wn*64 + g)*ROWW + t;

        #pragma unroll
        for (int ks=0; ks<16; ++ks){
            const int ko = ks*8;
            uint32_t a[2][4];
            #pragma unroll
            for (int mc=0;mc<2;mc++){
                const uint32_t* p = Ap + mc*16*ROWW + ko;
                a[mc][0]=p[0]; a[mc][1]=p[8*ROWW]; a[mc][2]=p[4]; a[mc][3]=p[8*ROWW+4];
            }
            uint32_t b[8][2];
            #pragma unroll
            for (int nc=0;nc<8;nc++){
                const uint32_t* p = Bp + nc*8*ROWW + ko;
                b[nc][0]=p[0]; b[nc][1]=p[4];
            }
            #pragma unroll
            for (int mc=0;mc<2;mc++)
                #pragma unroll
                for (int nc=0;nc<8;nc++)
                    asm volatile(
                        "mma.sync.aligned.m16n8k16.row.col.f32.bf16.bf16.f32 "
                        "{%0,%1,%2,%3}, {%4,%5,%6,%7}, {%8,%9}, {%0,%1,%2,%3};\n"
                        : "+f"(acc[mc][nc][0]),"+f"(acc[mc][nc][1]),
                          "+f"(acc[mc][nc][2]),"+f"(acc[mc][nc][3])
                        : "r"(a[mc][0]),"r"(a[mc][1]),"r"(a[mc][2]),"r"(a[mc][3]),
                          "r"(b[nc][0]),"r"(b[nc][1]));
        }

        // fused epilogue: exp((s-1)/t) and row-wise accumulation; reset accs
        #pragma unroll
        for (int mc=0;mc<2;mc++)
            #pragma unroll
            for (int nc=0;nc<8;nc++)
                #pragma unroll
                for (int i=0;i<4;i++){
                    float v = acc[mc][nc][i];
                    rowsum[mc*2 + (i>>1)] += ex2f_fast(fmaf(v, Kc, -Kc));
                    acc[mc][nc][i] = 0.f;
                }
        __syncthreads();   // all reads of this B buffer done before next issue reuses it
    }

    // reduce partial row sums across the 4 lanes sharing a row (t = lane&3)
    #pragma unroll
    for (int j=0;j<4;j++){
        rowsum[j] += __shfl_xor_sync(0xffffffffu, rowsum[j], 1);
        rowsum[j] += __shfl_xor_sync(0xffffffffu, rowsum[j], 2);
    }
    if (t == 0){
        #pragma unroll
        for (int j=0;j<4;j++){
            int mc = j>>1, h = j&1;
            int r = wm*32 + mc*16 + h*8 + g;
            atomicAdd(&rowsum_sm[r], rowsum[j]);   // merge across wn=0/1 warps
        }
    }
    __syncthreads();

    float val = 0.f;
    if (tid < TILE_M){
        int grow = cta*TILE_M + tid;
        val = logf(rowsum_sm[tid]) - g_Sv[grow];   // log(sum_exp) - (dot-1)/t
    }
    __syncthreads();
    #pragma unroll
    for (int o=16;o;o>>=1) val += __shfl_xor_sync(0xffffffffu, val, o);
    if (lane==0) red_sm[wid] = val;
    __syncthreads();
    if (tid==0){
        double s = 0.0;
        #pragma unroll
        for (int w=0;w<8;w++) s += (double)red_sm[w];
        atomicAdd(&g_acc, s);
    }
}

__global__ void finalize_kernel(float* __restrict__ out, int nrows){
    if (threadIdx.x==0 && blockIdx.x==0)
        out[0] = (float)(g_acc / (double)nrows);
}

extern "C" void kernel_launch(void* const* d_in, const int* in_sizes, int n_in,
                              void* d_out, int out_size){
    const float* X = (const float*)d_in[0];   // text_features
    const float* Y = (const float*)d_in[1];   // image_features
    float* out = (float*)d_out;
    int nrows = in_sizes[0] / DDIM;

    int nb = (nrows*32 + NTHREADS - 1) / NTHREADS;   // one warp per row
    norm_kernel<<<nb, NTHREADS>>>(X, 0, nrows);
    norm_kernel<<<nb, NTHREADS>>>(Y, 1, nrows);
    sv_kernel<<<nb, NTHREADS>>>(X, Y, nrows);

    cudaFuncSetAttribute(lit_main_kernel,
                         cudaFuncAttributeMaxDynamicSharedMemorySize, SMEM_BYTES);
    lit_main_kernel<<<nrows/TILE_M, NTHREADS, SMEM_BYTES>>>(nrows);

    finalize_kernel<<<1, 32>>>(out, nrows);
}